// round 1
// baseline (speedup 1.0000x reference)
#include <cuda_runtime.h>

#define CUR   512
#define FULLL 1024
#define BSZ   8
#define DIMM  1024
#define NH    16
#define HD    64
#define ATT_SCALE 0.125f   // 1/sqrt(64)

// ---------------- scratch (device globals; allocation-free) ----------------
__device__ float g_K [BSZ*NH*FULLL*HD];              // [b][h][f][d]
__device__ float g_V [BSZ*NH*FULLL*HD];              // [b][h][f][d]
__device__ float g_QU[BSZ*NH*CUR*HD];                // [b][h][c][d]  (q + u)
__device__ float g_QV[BSZ*NH*CUR*HD];                // [b][h][c][d]  (q + v)
__device__ float g_Rt[NH*HD*FULLL];                  // [h][d][t]  (R transposed)
__device__ float g_P [(size_t)BSZ*NH*CUR*FULLL];     // [bh][a][m] = (q+v)·r
__device__ float g_AV[CUR*BSZ*NH*HD];                // [c][b][h*d]

// ---------------- shared 128x128x16 fp32 GEMM core ----------------
// A: MxK row-major (lda), B: KxN row-major (ldb). 256 threads, 8x8 per thread.
__device__ __forceinline__ void gemm_tile(
    const float* __restrict__ A, const float* __restrict__ B,
    int K, int lda, int ldb, int row0, int col0, float acc[8][8])
{
    __shared__ float As[16][132];   // transposed A tile, padded
    __shared__ float Bs[16][132];
    const int tid = threadIdx.x;
    const int ty = tid >> 4, tx = tid & 15;

    float4 pa[2], pb[2];
    #pragma unroll
    for (int i = 0; i < 2; i++) {
        int s = tid + i*256;
        int ar = s >> 2, ac = (s & 3) << 2;
        pa[i] = *(const float4*)(A + (size_t)(row0 + ar)*lda + ac);
        int br = s >> 5, bc = (s & 31) << 2;
        pb[i] = *(const float4*)(B + (size_t)br*ldb + col0 + bc);
    }

    for (int kt = 0; kt < K; kt += 16) {
        #pragma unroll
        for (int i = 0; i < 2; i++) {
            int s = tid + i*256;
            int ar = s >> 2, ac = (s & 3) << 2;
            As[ac+0][ar] = pa[i].x; As[ac+1][ar] = pa[i].y;
            As[ac+2][ar] = pa[i].z; As[ac+3][ar] = pa[i].w;
            int br = s >> 5, bc = (s & 31) << 2;
            *(float4*)&Bs[br][bc] = pb[i];
        }
        __syncthreads();
        if (kt + 16 < K) {
            #pragma unroll
            for (int i = 0; i < 2; i++) {
                int s = tid + i*256;
                int ar = s >> 2, ac = (s & 3) << 2;
                pa[i] = *(const float4*)(A + (size_t)(row0 + ar)*lda + (kt + 16 + ac));
                int br = s >> 5, bc = (s & 31) << 2;
                pb[i] = *(const float4*)(B + (size_t)(kt + 16 + br)*ldb + col0 + bc);
            }
        }
        #pragma unroll
        for (int k = 0; k < 16; k++) {
            float af[8], bf[8];
            *(float4*)&af[0] = *(const float4*)&As[k][ty*8];
            *(float4*)&af[4] = *(const float4*)&As[k][ty*8 + 4];
            *(float4*)&bf[0] = *(const float4*)&Bs[k][tx*8];
            *(float4*)&bf[4] = *(const float4*)&Bs[k][tx*8 + 4];
            #pragma unroll
            for (int i = 0; i < 8; i++)
                #pragma unroll
                for (int j = 0; j < 8; j++)
                    acc[i][j] = fmaf(af[i], bf[j], acc[i][j]);
        }
        __syncthreads();
    }
}

// ---------------- KV projection: full_input @ W_kv + b_kv -> g_K, g_V ----------------
__global__ __launch_bounds__(256) void k_gemm_kv(
    const float* __restrict__ X, const float* __restrict__ W, const float* __restrict__ bias)
{
    float acc[8][8] = {};
    int row0 = blockIdx.y * 128, col0 = blockIdx.x * 128;
    gemm_tile(X, W, DIMM, DIMM, 2*NH*HD, row0, col0, acc);
    int ty = threadIdx.x >> 4, tx = threadIdx.x & 15;
    bool isK = (col0 < NH*HD);
    float* dst = isK ? g_K : g_V;
    int cbase = isK ? col0 : (col0 - NH*HD);
    #pragma unroll
    for (int i = 0; i < 8; i++) {
        int m = row0 + ty*8 + i;
        int f = m >> 3, b = m & 7;
        #pragma unroll
        for (int j = 0; j < 8; j++) {
            int n = cbase + tx*8 + j;
            int h = n >> 6, d = n & 63;
            dst[(((b*NH + h)*FULLL) + f)*HD + d] = acc[i][j] + bias[col0 + tx*8 + j];
        }
    }
}

// ---------------- Q projection: inputs @ W_q + b_q ; write q+u and q+v ----------------
__global__ __launch_bounds__(256) void k_gemm_q(
    const float* __restrict__ X, const float* __restrict__ W, const float* __restrict__ bias,
    const float* __restrict__ u, const float* __restrict__ v)
{
    float acc[8][8] = {};
    int row0 = blockIdx.y * 128, col0 = blockIdx.x * 128;
    gemm_tile(X, W, DIMM, DIMM, NH*HD, row0, col0, acc);
    int ty = threadIdx.x >> 4, tx = threadIdx.x & 15;
    #pragma unroll
    for (int i = 0; i < 8; i++) {
        int m = row0 + ty*8 + i;
        int c = m >> 3, b = m & 7;
        #pragma unroll
        for (int j = 0; j < 8; j++) {
            int n = col0 + tx*8 + j;
            int h = n >> 6, d = n & 63;
            float q = acc[i][j] + bias[n];
            int idx = (((b*NH + h)*CUR) + c)*HD + d;
            g_QU[idx] = q + u[n];
            g_QV[idx] = q + v[n];
        }
    }
}

// ---------------- R projection: pos_embedding @ W_pos + b_pos -> g_Rt [h][d][t] ----------------
__global__ __launch_bounds__(256) void k_gemm_r(
    const float* __restrict__ X, const float* __restrict__ W, const float* __restrict__ bias)
{
    float acc[8][8] = {};
    int row0 = blockIdx.y * 128, col0 = blockIdx.x * 128;
    gemm_tile(X, W, DIMM, DIMM, NH*HD, row0, col0, acc);
    int ty = threadIdx.x >> 4, tx = threadIdx.x & 15;
    #pragma unroll
    for (int i = 0; i < 8; i++) {
        int t = row0 + ty*8 + i;
        #pragma unroll
        for (int j = 0; j < 8; j++) {
            int n = col0 + tx*8 + j;
            int h = n >> 6, d = n & 63;
            g_Rt[(h*HD + d)*FULLL + t] = acc[i][j] + bias[n];
        }
    }
}

// ---------------- P = QV_bh (512x64) @ Rt_h (64x1024) per (b,h) ----------------
__global__ __launch_bounds__(256) void k_gemm_p()
{
    int bh = blockIdx.z;
    int h = bh & 15;
    const float* A = g_QV + (size_t)bh * CUR * HD;
    const float* B = g_Rt + (size_t)h * HD * FULLL;
    float acc[8][8] = {};
    int row0 = blockIdx.y * 128, col0 = blockIdx.x * 128;
    gemm_tile(A, B, HD, HD, FULLL, row0, col0, acc);
    float* Pp = g_P + (size_t)bh * CUR * FULLL;
    int ty = threadIdx.x >> 4, tx = threadIdx.x & 15;
    #pragma unroll
    for (int i = 0; i < 8; i++) {
        int a = row0 + ty*8 + i;
        float* row = Pp + (size_t)a * FULLL + col0 + tx*8;
        *(float4*)(row)     = make_float4(acc[i][0], acc[i][1], acc[i][2], acc[i][3]);
        *(float4*)(row + 4) = make_float4(acc[i][4], acc[i][5], acc[i][6], acc[i][7]);
    }
}

// ---------------- fused flash attention ----------------
// grid (8 q-tiles, 128 bh), 256 threads, dynamic smem 86016B.
// S[a][j] = (QU[a]·K[j] + P[a][j+511-a]) * SCALE, masked when j-a > 512.
__global__ __launch_bounds__(256) void k_attn()
{
    const int bh = blockIdx.y;
    const int b = bh >> 4, h = bh & 15;
    const int a0 = blockIdx.x * 64;
    extern __shared__ float sm[];
    float* sQU = sm;                        // [64][68]
    float* sKV = sm + 64*68;                // [128][68]  (K, then reused for V)
    float* sP  = sm + 64*68 + 128*68;       // [64][132]

    const int tid = threadIdx.x;
    const int ty = tid >> 4, tx = tid & 15;

    const float* QUb = g_QU + ((size_t)bh * CUR + a0) * HD;
    const float* Kb  = g_K + (size_t)bh * FULLL * HD;
    const float* Vb  = g_V + (size_t)bh * FULLL * HD;
    const float* Pb  = g_P + (size_t)bh * CUR * FULLL;

    #pragma unroll
    for (int t = 0; t < 4; t++) {
        int s = tid + t*256;
        int r = s >> 4, d0 = (s & 15) << 2;
        *(float4*)&sQU[r*68 + d0] = *(const float4*)(QUb + r*HD + d0);
    }

    float acc_o[4][4] = {};
    float row_m[4], row_l[4];
    #pragma unroll
    for (int i = 0; i < 4; i++) { row_m[i] = -1e30f; row_l[i] = 0.f; }

    const int nkb = (a0 + 703) >> 7;   // ceil((a0+576)/128)
    for (int kb = 0; kb < nkb; kb++) {
        const int j0 = kb << 7;
        __syncthreads();   // protect sKV/sP reuse from previous iter (and sQU on first)
        #pragma unroll
        for (int t = 0; t < 8; t++) {
            int s = tid + t*256;
            int r = s >> 4, d0 = (s & 15) << 2;
            *(float4*)&sKV[r*68 + d0] = *(const float4*)(Kb + (size_t)(j0 + r)*HD + d0);
        }
        // gather shifted position scores from P (global, guarded)
        float pos[4][8];
        #pragma unroll
        for (int i = 0; i < 4; i++) {
            int a = a0 + ty*4 + i;
            const float* Pr = Pb + (size_t)a * FULLL;
            #pragma unroll
            for (int jj = 0; jj < 8; jj++) {
                int j = j0 + tx*8 + jj;
                int m = j + (CUR - 1) - a;
                pos[i][jj] = (m < FULLL) ? Pr[m] : 0.f;
            }
        }
        __syncthreads();
        // content scores: QU tile @ K tile^T
        float s_t[4][8] = {};
        #pragma unroll
        for (int k = 0; k < HD; k += 2) {
            float2 af[4], kf[8];
            #pragma unroll
            for (int i = 0; i < 4; i++)  af[i] = *(const float2*)&sQU[(ty*4+i)*68 + k];
            #pragma unroll
            for (int jj = 0; jj < 8; jj++) kf[jj] = *(const float2*)&sKV[(tx*8+jj)*68 + k];
            #pragma unroll
            for (int i = 0; i < 4; i++)
                #pragma unroll
                for (int jj = 0; jj < 8; jj++)
                    s_t[i][jj] += af[i].x*kf[jj].x + af[i].y*kf[jj].y;
        }
        // combine + mask + online softmax (row groups = 16 tx lanes)
        #pragma unroll
        for (int i = 0; i < 4; i++) {
            int a = a0 + ty*4 + i;
            float mx = -1e30f;
            #pragma unroll
            for (int jj = 0; jj < 8; jj++) {
                int j = j0 + tx*8 + jj;
                int m = j + (CUR - 1) - a;
                float sv = (m < FULLL) ? (s_t[i][jj] + pos[i][jj]) * ATT_SCALE : -1e30f;
                s_t[i][jj] = sv;
                mx = fmaxf(mx, sv);
            }
            #pragma unroll
            for (int off = 1; off < 16; off <<= 1)
                mx = fmaxf(mx, __shfl_xor_sync(0xffffffffu, mx, off));
            float mnew = fmaxf(row_m[i], mx);
            float corr = __expf(row_m[i] - mnew);
            row_m[i] = mnew;
            float ls = 0.f;
            #pragma unroll
            for (int jj = 0; jj < 8; jj++) {
                float p = __expf(s_t[i][jj] - mnew);
                s_t[i][jj] = p;
                ls += p;
            }
            #pragma unroll
            for (int off = 1; off < 16; off <<= 1)
                ls += __shfl_xor_sync(0xffffffffu, ls, off);
            row_l[i] = row_l[i]*corr + ls;
            #pragma unroll
            for (int c = 0; c < 4; c++) acc_o[i][c] *= corr;
        }
        __syncthreads();   // all K reads done; reuse sKV for V
        #pragma unroll
        for (int i = 0; i < 4; i++) {
            *(float4*)&sP[(ty*4+i)*132 + tx*8]     = make_float4(s_t[i][0], s_t[i][1], s_t[i][2], s_t[i][3]);
            *(float4*)&sP[(ty*4+i)*132 + tx*8 + 4] = make_float4(s_t[i][4], s_t[i][5], s_t[i][6], s_t[i][7]);
        }
        #pragma unroll
        for (int t = 0; t < 8; t++) {
            int s = tid + t*256;
            int r = s >> 4, d0 = (s & 15) << 2;
            *(float4*)&sKV[r*68 + d0] = *(const float4*)(Vb + (size_t)(j0 + r)*HD + d0);
        }
        __syncthreads();
        // O += P @ V
        for (int j = 0; j < 128; j += 2) {
            float2 pf[4];
            #pragma unroll
            for (int i = 0; i < 4; i++) pf[i] = *(const float2*)&sP[(ty*4+i)*132 + j];
            float4 v0 = *(const float4*)&sKV[j*68 + tx*4];
            float4 v1 = *(const float4*)&sKV[(j+1)*68 + tx*4];
            #pragma unroll
            for (int i = 0; i < 4; i++) {
                acc_o[i][0] += pf[i].x*v0.x + pf[i].y*v1.x;
                acc_o[i][1] += pf[i].x*v0.y + pf[i].y*v1.y;
                acc_o[i][2] += pf[i].x*v0.z + pf[i].y*v1.z;
                acc_o[i][3] += pf[i].x*v0.w + pf[i].y*v1.w;
            }
        }
    }
    #pragma unroll
    for (int i = 0; i < 4; i++) {
        int a = a0 + ty*4 + i;
        float inv = 1.f / row_l[i];
        float4 o = make_float4(acc_o[i][0]*inv, acc_o[i][1]*inv, acc_o[i][2]*inv, acc_o[i][3]*inv);
        *(float4*)&g_AV[((size_t)a*BSZ + b)*(NH*HD) + h*HD + tx*4] = o;
    }
}

// ---------------- output projection: AV @ W_proj + b_proj -> out ----------------
__global__ __launch_bounds__(256) void k_gemm_proj(
    const float* __restrict__ W, const float* __restrict__ bias, float* __restrict__ out)
{
    float acc[8][8] = {};
    int row0 = blockIdx.y * 128, col0 = blockIdx.x * 128;
    gemm_tile(g_AV, W, NH*HD, NH*HD, DIMM, row0, col0, acc);
    int ty = threadIdx.x >> 4, tx = threadIdx.x & 15;
    #pragma unroll
    for (int i = 0; i < 8; i++) {
        int m = row0 + ty*8 + i;
        float* orow = out + (size_t)m * DIMM + col0 + tx*8;
        float4 o0 = make_float4(acc[i][0] + bias[col0+tx*8+0], acc[i][1] + bias[col0+tx*8+1],
                                acc[i][2] + bias[col0+tx*8+2], acc[i][3] + bias[col0+tx*8+3]);
        float4 o1 = make_float4(acc[i][4] + bias[col0+tx*8+4], acc[i][5] + bias[col0+tx*8+5],
                                acc[i][6] + bias[col0+tx*8+6], acc[i][7] + bias[col0+tx*8+7]);
        *(float4*)(orow)     = o0;
        *(float4*)(orow + 4) = o1;
    }
}

// ---------------- launch ----------------
extern "C" void kernel_launch(void* const* d_in, const int* in_sizes, int n_in,
                              void* d_out, int out_size)
{
    const float* inputs     = (const float*)d_in[0];
    const float* pos_emb    = (const float*)d_in[1];
    const float* full_input = (const float*)d_in[2];
    const float* u          = (const float*)d_in[3];
    const float* v          = (const float*)d_in[4];
    // d_in[5] = mask: unused (mask derived analytically from rel-shift algebra)
    const float* W_kv   = (const float*)d_in[6];
    const float* b_kv   = (const float*)d_in[7];
    const float* W_q    = (const float*)d_in[8];
    const float* b_q    = (const float*)d_in[9];
    const float* W_pos  = (const float*)d_in[10];
    const float* b_pos  = (const float*)d_in[11];
    const float* W_proj = (const float*)d_in[12];
    const float* b_proj = (const float*)d_in[13];
    float* out = (float*)d_out;

    cudaFuncSetAttribute(k_attn, cudaFuncAttributeMaxDynamicSharedMemorySize, 86016);

    k_gemm_kv  <<<dim3(16, 64),      256>>>(full_input, W_kv, b_kv);
    k_gemm_q   <<<dim3(8, 32),       256>>>(inputs, W_q, b_q, u, v);
    k_gemm_r   <<<dim3(8, 8),        256>>>(pos_emb, W_pos, b_pos);
    k_gemm_p   <<<dim3(8, 4, 128),   256>>>();
    k_attn     <<<dim3(8, 128),      256, 86016>>>();
    k_gemm_proj<<<dim3(8, 32),       256>>>(W_proj, b_proj, out);
}

// round 3
// speedup vs baseline: 1.5191x; 1.5191x over previous
#include <cuda_runtime.h>
#include <cuda_bf16.h>
#include <stdint.h>

#define CUR   512
#define FULLL 1024
#define BSZ   8
#define DIMM  1024
#define NH    16
#define HD    64
#define ATT_SCALE 0.125f

// ---------------- scratch (device globals; allocation-free) ----------------
__device__ float g_K [BSZ*NH*FULLL*HD];
__device__ float g_V [BSZ*NH*FULLL*HD];
__device__ float g_QU[BSZ*NH*CUR*HD];
__device__ __nv_bfloat16 g_QVh[BSZ*NH*CUR*HD], g_QVl[BSZ*NH*CUR*HD];
__device__ __nv_bfloat16 g_Rh [NH*FULLL*HD],   g_Rl [NH*FULLL*HD];
__device__ float g_P [(size_t)BSZ*NH*CUR*FULLL];
__device__ float g_AV[CUR*BSZ*NH*HD];
__device__ __nv_bfloat16 g_Ah[8192*1024], g_Al[8192*1024];   // A operand (split)
__device__ __nv_bfloat16 g_Wh[2048*1024], g_Wl[2048*1024];   // B operand (W^T split)
__device__ float g_C[(size_t)8192*2048];                     // GEMM output

// ---------------- helpers ----------------
__device__ __forceinline__ uint32_t smem_u32(const void* p){
    uint32_t a; asm("{ .reg .u64 t; cvta.to.shared.u64 t, %1; cvt.u32.u64 %0, t; }":"=r"(a):"l"(p)); return a;
}
__device__ __forceinline__ void ldsm4(uint32_t* r, uint32_t addr){
    asm volatile("ldmatrix.sync.aligned.m8n8.x4.shared.b16 {%0,%1,%2,%3}, [%4];"
        : "=r"(r[0]),"=r"(r[1]),"=r"(r[2]),"=r"(r[3]) : "r"(addr));
}
__device__ __forceinline__ void mma_bf16(float* c, const uint32_t* a, uint32_t b0, uint32_t b1){
    asm volatile("mma.sync.aligned.m16n8k16.row.col.f32.bf16.bf16.f32 "
        "{%0,%1,%2,%3}, {%4,%5,%6,%7}, {%8,%9}, {%0,%1,%2,%3};"
        : "+f"(c[0]),"+f"(c[1]),"+f"(c[2]),"+f"(c[3])
        : "r"(a[0]),"r"(a[1]),"r"(a[2]),"r"(a[3]), "r"(b0),"r"(b1));
}

// ---------------- warp-MMA bf16x3 GEMM core ----------------
// C[128,128] = A[128,K] @ B[128,K]^T. A,B row-major [rows][K] bf16 (hi+lo).
// 256 threads = 8 warps (2m x 4n), warp tile 64x32. K multiple of 64.
#define TSTR 72                 // smem row stride (elements)
#define TILE_ELEMS (128*TSTR)   // 9216
#define SM_BYTES (4*TILE_ELEMS*2)   // 73728

__device__ __forceinline__ void load_tile(__nv_bfloat16* dst, const __nv_bfloat16* src, int ld){
    const int tid = threadIdx.x;
    #pragma unroll
    for (int i = 0; i < 4; i++) {
        int s = tid + (i<<8);
        int row = s >> 3, cq = s & 7;
        *(float4*)(dst + row*TSTR + cq*8) = *(const float4*)(src + (size_t)row*ld + cq*8);
    }
}

__device__ void gemm_core(const __nv_bfloat16* Ah, const __nv_bfloat16* Al,
                          const __nv_bfloat16* Bh, const __nv_bfloat16* Bl,
                          float* C, int K, int ldc, int m0, int n0)
{
    extern __shared__ __nv_bfloat16 smb[];
    __nv_bfloat16* sAh = smb;
    __nv_bfloat16* sAl = smb + TILE_ELEMS;
    __nv_bfloat16* sBh = smb + 2*TILE_ELEMS;
    __nv_bfloat16* sBl = smb + 3*TILE_ELEMS;
    const uint32_t bAh = smem_u32(sAh), bAl = smem_u32(sAl);
    const uint32_t bBh = smem_u32(sBh), bBl = smem_u32(sBl);

    const int tid = threadIdx.x;
    const int lane = tid & 31, wid = tid >> 5;
    const int wm = wid >> 2, wn = wid & 3;
    const int g = lane >> 3, lr = lane & 7;

    // ldmatrix per-lane address bases (byte offsets into each tile)
    const int arow = wm*64 + lr + (g & 1)*8;
    const int kcol = (g >> 1)*8;
    uint32_t aoff[4];
    #pragma unroll
    for (int mf = 0; mf < 4; mf++) aoff[mf] = (uint32_t)(((arow + mf*16)*TSTR + kcol)*2);
    const int brow = wn*32 + lr + (g & 1)*8;
    uint32_t boff[2];
    #pragma unroll
    for (int np = 0; np < 2; np++) boff[np] = (uint32_t)(((brow + np*16)*TSTR + kcol)*2);

    float acc[4][4][4] = {};

    const __nv_bfloat16* pAh = Ah + (size_t)m0 * K;
    const __nv_bfloat16* pAl = Al + (size_t)m0 * K;
    const __nv_bfloat16* pBh = Bh + (size_t)n0 * K;
    const __nv_bfloat16* pBl = Bl + (size_t)n0 * K;

    const int nchunk = K >> 6;
    for (int kc = 0; kc < nchunk; kc++) {
        const int k0 = kc << 6;
        __syncthreads();
        load_tile(sAh, pAh + k0, K);
        load_tile(sAl, pAl + k0, K);
        load_tile(sBh, pBh + k0, K);
        load_tile(sBl, pBl + k0, K);
        __syncthreads();
        #pragma unroll
        for (int ks = 0; ks < 4; ks++) {
            const uint32_t kb = ks*32;   // 16 elems * 2B
            uint32_t ah[4][4], al[4][4], bp[2][4];
            #pragma unroll
            for (int mf = 0; mf < 4; mf++) {
                ldsm4(ah[mf], bAh + aoff[mf] + kb);
                ldsm4(al[mf], bAl + aoff[mf] + kb);
            }
            ldsm4(bp[0], bBh + boff[0] + kb);
            ldsm4(bp[1], bBh + boff[1] + kb);
            #pragma unroll
            for (int mf = 0; mf < 4; mf++)
                #pragma unroll
                for (int nf = 0; nf < 4; nf++)
                    mma_bf16(acc[mf][nf], ah[mf], bp[nf>>1][nf&1], bp[nf>>1][2+(nf&1)]);
            #pragma unroll
            for (int mf = 0; mf < 4; mf++)
                #pragma unroll
                for (int nf = 0; nf < 4; nf++)
                    mma_bf16(acc[mf][nf], al[mf], bp[nf>>1][nf&1], bp[nf>>1][2+(nf&1)]);
            ldsm4(bp[0], bBl + boff[0] + kb);
            ldsm4(bp[1], bBl + boff[1] + kb);
            #pragma unroll
            for (int mf = 0; mf < 4; mf++)
                #pragma unroll
                for (int nf = 0; nf < 4; nf++)
                    mma_bf16(acc[mf][nf], ah[mf], bp[nf>>1][nf&1], bp[nf>>1][2+(nf&1)]);
        }
    }

    const int r0 = m0 + wm*64 + (lane >> 2);
    const int c0 = n0 + wn*32 + (lane & 3)*2;
    #pragma unroll
    for (int mf = 0; mf < 4; mf++)
        #pragma unroll
        for (int nf = 0; nf < 4; nf++) {
            float* p = C + (size_t)(r0 + mf*16)*ldc + c0 + nf*8;
            *(float2*)p              = make_float2(acc[mf][nf][0], acc[mf][nf][1]);
            *(float2*)(p + 8*ldc)    = make_float2(acc[mf][nf][2], acc[mf][nf][3]);
        }
}

__global__ __launch_bounds__(256, 2) void k_gemm_main(int K, int ldc) {
    gemm_core(g_Ah, g_Al, g_Wh, g_Wl, g_C, K, ldc, blockIdx.y*128, blockIdx.x*128);
}
__global__ __launch_bounds__(256, 2) void k_gemm_pos() {
    int bh = blockIdx.z, h = bh & 15;
    gemm_core(g_QVh + (size_t)bh*CUR*HD, g_QVl + (size_t)bh*CUR*HD,
              g_Rh  + (size_t)h*FULLL*HD, g_Rl + (size_t)h*FULLL*HD,
              g_P   + (size_t)bh*CUR*FULLL, HD, FULLL, blockIdx.y*128, blockIdx.x*128);
}

// ---------------- conversion / reshape kernels ----------------
__device__ __forceinline__ void bfsplit(float x, __nv_bfloat16& h, __nv_bfloat16& l){
    h = __float2bfloat16(x);
    l = __float2bfloat16(x - __bfloat162float(h));
}

__global__ __launch_bounds__(256) void k_split(const float* __restrict__ src, int n){
    int i = (blockIdx.x*256 + threadIdx.x) * 4;
    if (i >= n) return;
    float4 v = *(const float4*)(src + i);
    __nv_bfloat16 h, l;
    bfsplit(v.x, h, l); g_Ah[i+0]=h; g_Al[i+0]=l;
    bfsplit(v.y, h, l); g_Ah[i+1]=h; g_Al[i+1]=l;
    bfsplit(v.z, h, l); g_Ah[i+2]=h; g_Al[i+2]=l;
    bfsplit(v.w, h, l); g_Ah[i+3]=h; g_Al[i+3]=l;
}
__global__ __launch_bounds__(256) void k_split_av(){
    int i = (blockIdx.x*256 + threadIdx.x) * 4;
    float4 v = *(const float4*)(g_AV + i);
    __nv_bfloat16 h, l;
    bfsplit(v.x, h, l); g_Ah[i+0]=h; g_Al[i+0]=l;
    bfsplit(v.y, h, l); g_Ah[i+1]=h; g_Al[i+1]=l;
    bfsplit(v.z, h, l); g_Ah[i+2]=h; g_Al[i+2]=l;
    bfsplit(v.w, h, l); g_Ah[i+3]=h; g_Al[i+3]=l;
}
// W [K][N] fp32 -> g_Wh/g_Wl [N][K] bf16
__global__ __launch_bounds__(256) void k_tsplit(const float* __restrict__ W, int K, int N){
    __shared__ float t[32][33];
    int k0 = blockIdx.y*32, n0 = blockIdx.x*32;
    int tx = threadIdx.x & 31, ty = threadIdx.x >> 5;
    #pragma unroll
    for (int i = 0; i < 32; i += 8)
        t[ty+i][tx] = W[(size_t)(k0+ty+i)*N + n0+tx];
    __syncthreads();
    #pragma unroll
    for (int i = 0; i < 32; i += 8) {
        float v = t[tx][ty+i];
        __nv_bfloat16 h, l; bfsplit(v, h, l);
        size_t o = (size_t)(n0+ty+i)*K + k0+tx;
        g_Wh[o] = h; g_Wl[o] = l;
    }
}
__global__ __launch_bounds__(256) void k_reshape_kv(const float* __restrict__ bias){
    size_t i = ((size_t)blockIdx.x*256 + threadIdx.x) * 4;
    int m = (int)(i >> 11), n = (int)(i & 2047);
    int f = m >> 3, b = m & 7;
    bool isK = n < 1024;
    int nn = isK ? n : n - 1024;
    int h = nn >> 6, d = nn & 63;
    float4 v = *(const float4*)(g_C + i);
    v.x += bias[n]; v.y += bias[n+1]; v.z += bias[n+2]; v.w += bias[n+3];
    float* dst = (isK ? g_K : g_V) + (((size_t)(b*NH + h)*FULLL) + f)*HD + d;
    *(float4*)dst = v;
}
__global__ __launch_bounds__(256) void k_reshape_q(const float* __restrict__ bias,
                                                   const float* __restrict__ u,
                                                   const float* __restrict__ v){
    size_t i = ((size_t)blockIdx.x*256 + threadIdx.x) * 4;
    int m = (int)(i >> 10), n = (int)(i & 1023);
    int c = m >> 3, b = m & 7;
    int h = n >> 6, d = n & 63;
    float4 q = *(const float4*)(g_C + i);
    q.x += bias[n]; q.y += bias[n+1]; q.z += bias[n+2]; q.w += bias[n+3];
    size_t o = (((size_t)(b*NH + h)*CUR) + c)*HD + d;
    *(float4*)(g_QU + o) = make_float4(q.x+u[n], q.y+u[n+1], q.z+u[n+2], q.w+u[n+3]);
    __nv_bfloat16 hh, ll;
    bfsplit(q.x + v[n],   hh, ll); g_QVh[o+0]=hh; g_QVl[o+0]=ll;
    bfsplit(q.y + v[n+1], hh, ll); g_QVh[o+1]=hh; g_QVl[o+1]=ll;
    bfsplit(q.z + v[n+2], hh, ll); g_QVh[o+2]=hh; g_QVl[o+2]=ll;
    bfsplit(q.w + v[n+3], hh, ll); g_QVh[o+3]=hh; g_QVl[o+3]=ll;
}
__global__ __launch_bounds__(256) void k_reshape_r(const float* __restrict__ bias){
    size_t i = ((size_t)blockIdx.x*256 + threadIdx.x) * 4;
    int t = (int)(i >> 10), n = (int)(i & 1023);
    int h = n >> 6, d = n & 63;
    float4 q = *(const float4*)(g_C + i);
    q.x += bias[n]; q.y += bias[n+1]; q.z += bias[n+2]; q.w += bias[n+3];
    size_t o = ((size_t)h*FULLL + t)*HD + d;
    __nv_bfloat16 hh, ll;
    bfsplit(q.x, hh, ll); g_Rh[o+0]=hh; g_Rl[o+0]=ll;
    bfsplit(q.y, hh, ll); g_Rh[o+1]=hh; g_Rl[o+1]=ll;
    bfsplit(q.z, hh, ll); g_Rh[o+2]=hh; g_Rl[o+2]=ll;
    bfsplit(q.w, hh, ll); g_Rh[o+3]=hh; g_Rl[o+3]=ll;
}
__global__ __launch_bounds__(256) void k_biasout(const float* __restrict__ bias, float* __restrict__ out){
    size_t i = ((size_t)blockIdx.x*256 + threadIdx.x) * 4;
    int n = (int)(i & 1023);
    float4 q = *(const float4*)(g_C + i);
    *(float4*)(out + i) = make_float4(q.x+bias[n], q.y+bias[n+1], q.z+bias[n+2], q.w+bias[n+3]);
}

// ---------------- fused flash attention (fp32 SIMT) ----------------
__global__ __launch_bounds__(256) void k_attn()
{
    const int bh = blockIdx.y;
    const int b = bh >> 4, h = bh & 15;
    const int a0 = blockIdx.x * 64;
    extern __shared__ float smf[];
    float* sQU = smf;
    float* sKV = smf + 64*68;
    float* sP  = smf + 64*68 + 128*68;

    const int tid = threadIdx.x;
    const int ty = tid >> 4, tx = tid & 15;

    const float* QUb = g_QU + ((size_t)bh * CUR + a0) * HD;
    const float* Kb  = g_K + (size_t)bh * FULLL * HD;
    const float* Vb  = g_V + (size_t)bh * FULLL * HD;
    const float* Pb  = g_P + (size_t)bh * CUR * FULLL;

    #pragma unroll
    for (int t = 0; t < 4; t++) {
        int s = tid + t*256;
        int r = s >> 4, d0 = (s & 15) << 2;
        *(float4*)&sQU[r*68 + d0] = *(const float4*)(QUb + r*HD + d0);
    }

    float acc_o[4][4] = {};
    float row_m[4], row_l[4];
    #pragma unroll
    for (int i = 0; i < 4; i++) { row_m[i] = -1e30f; row_l[i] = 0.f; }

    const int nkb = (a0 + 703) >> 7;
    for (int kb = 0; kb < nkb; kb++) {
        const int j0 = kb << 7;
        __syncthreads();
        #pragma unroll
        for (int t = 0; t < 8; t++) {
            int s = tid + t*256;
            int r = s >> 4, d0 = (s & 15) << 2;
            *(float4*)&sKV[r*68 + d0] = *(const float4*)(Kb + (size_t)(j0 + r)*HD + d0);
        }
        float pos[4][8];
        #pragma unroll
        for (int i = 0; i < 4; i++) {
            int a = a0 + ty*4 + i;
            const float* Pr = Pb + (size_t)a * FULLL;
            #pragma unroll
            for (int jj = 0; jj < 8; jj++) {
                int j = j0 + tx*8 + jj;
                int m = j + (CUR - 1) - a;
                pos[i][jj] = (m < FULLL) ? Pr[m] : 0.f;
            }
        }
        __syncthreads();
        float s_t[4][8] = {};
        #pragma unroll
        for (int k = 0; k < HD; k += 2) {
            float2 af[4], kf[8];
            #pragma unroll
            for (int i = 0; i < 4; i++)  af[i] = *(const float2*)&sQU[(ty*4+i)*68 + k];
            #pragma unroll
            for (int jj = 0; jj < 8; jj++) kf[jj] = *(const float2*)&sKV[(tx*8+jj)*68 + k];
            #pragma unroll
            for (int i = 0; i < 4; i++)
                #pragma unroll
                for (int jj = 0; jj < 8; jj++)
                    s_t[i][jj] += af[i].x*kf[jj].x + af[i].y*kf[jj].y;
        }
        #pragma unroll
        for (int i = 0; i < 4; i++) {
            int a = a0 + ty*4 + i;
            float mx = -1e30f;
            #pragma unroll
            for (int jj = 0; jj < 8; jj++) {
                int j = j0 + tx*8 + jj;
                int m = j + (CUR - 1) - a;
                float sv = (m < FULLL) ? (s_t[i][jj] + pos[i][jj]) * ATT_SCALE : -1e30f;
                s_t[i][jj] = sv;
                mx = fmaxf(mx, sv);
            }
            #pragma unroll
            for (int off = 1; off < 16; off <<= 1)
                mx = fmaxf(mx, __shfl_xor_sync(0xffffffffu, mx, off));
            float mnew = fmaxf(row_m[i], mx);
            float corr = __expf(row_m[i] - mnew);
            row_m[i] = mnew;
            float ls = 0.f;
            #pragma unroll
            for (int jj = 0; jj < 8; jj++) {
                float p = __expf(s_t[i][jj] - mnew);
                s_t[i][jj] = p;
                ls += p;
            }
            #pragma unroll
            for (int off = 1; off < 16; off <<= 1)
                ls += __shfl_xor_sync(0xffffffffu, ls, off);
            row_l[i] = row_l[i]*corr + ls;
            #pragma unroll
            for (int c = 0; c < 4; c++) acc_o[i][c] *= corr;
        }
        __syncthreads();
        #pragma unroll
        for (int i = 0; i < 4; i++) {
            *(float4*)&sP[(ty*4+i)*132 + tx*8]     = make_float4(s_t[i][0], s_t[i][1], s_t[i][2], s_t[i][3]);
            *(float4*)&sP[(ty*4+i)*132 + tx*8 + 4] = make_float4(s_t[i][4], s_t[i][5], s_t[i][6], s_t[i][7]);
        }
        #pragma unroll
        for (int t = 0; t < 8; t++) {
            int s = tid + t*256;
            int r = s >> 4, d0 = (s & 15) << 2;
            *(float4*)&sKV[r*68 + d0] = *(const float4*)(Vb + (size_t)(j0 + r)*HD + d0);
        }
        __syncthreads();
        for (int j = 0; j < 128; j += 2) {
            float2 pf[4];
            #pragma unroll
            for (int i = 0; i < 4; i++) pf[i] = *(const float2*)&sP[(ty*4+i)*132 + j];
            float4 v0 = *(const float4*)&sKV[j*68 + tx*4];
            float4 v1 = *(const float4*)&sKV[(j+1)*68 + tx*4];
            #pragma unroll
            for (int i = 0; i < 4; i++) {
                acc_o[i][0] += pf[i].x*v0.x + pf[i].y*v1.x;
                acc_o[i][1] += pf[i].x*v0.y + pf[i].y*v1.y;
                acc_o[i][2] += pf[i].x*v0.z + pf[i].y*v1.z;
                acc_o[i][3] += pf[i].x*v0.w + pf[i].y*v1.w;
            }
        }
    }
    #pragma unroll
    for (int i = 0; i < 4; i++) {
        int a = a0 + ty*4 + i;
        float inv = 1.f / row_l[i];
        float4 o = make_float4(acc_o[i][0]*inv, acc_o[i][1]*inv, acc_o[i][2]*inv, acc_o[i][3]*inv);
        *(float4*)&g_AV[((size_t)a*BSZ + b)*(NH*HD) + h*HD + tx*4] = o;
    }
}

// ---------------- launch ----------------
extern "C" void kernel_launch(void* const* d_in, const int* in_sizes, int n_in,
                              void* d_out, int out_size)
{
    const float* inputs     = (const float*)d_in[0];
    const float* pos_emb    = (const float*)d_in[1];
    const float* full_input = (const float*)d_in[2];
    const float* u          = (const float*)d_in[3];
    const float* v          = (const float*)d_in[4];
    // d_in[5] = mask: unused (derived analytically)
    const float* W_kv   = (const float*)d_in[6];
    const float* b_kv   = (const float*)d_in[7];
    const float* W_q    = (const float*)d_in[8];
    const float* b_q    = (const float*)d_in[9];
    const float* W_pos  = (const float*)d_in[10];
    const float* b_pos  = (const float*)d_in[11];
    const float* W_proj = (const float*)d_in[12];
    const float* b_proj = (const float*)d_in[13];
    float* out = (float*)d_out;

    cudaFuncSetAttribute(k_gemm_main, cudaFuncAttributeMaxDynamicSharedMemorySize, SM_BYTES);
    cudaFuncSetAttribute(k_gemm_pos,  cudaFuncAttributeMaxDynamicSharedMemorySize, SM_BYTES);
    cudaFuncSetAttribute(k_attn,      cudaFuncAttributeMaxDynamicSharedMemorySize, 86016);

    // KV projection
    k_tsplit<<<dim3(2048/32, 1024/32), 256>>>(W_kv, 1024, 2048);
    k_split <<<8192*1024/1024, 256>>>(full_input, 8192*1024);
    k_gemm_main<<<dim3(16, 64), 256, SM_BYTES>>>(1024, 2048);
    k_reshape_kv<<<8192*2048/1024, 256>>>(b_kv);

    // Q projection
    k_tsplit<<<dim3(32, 32), 256>>>(W_q, 1024, 1024);
    k_split <<<4096*1024/1024, 256>>>(inputs, 4096*1024);
    k_gemm_main<<<dim3(8, 32), 256, SM_BYTES>>>(1024, 1024);
    k_reshape_q<<<4096*1024/1024, 256>>>(b_q, u, v);

    // R projection
    k_tsplit<<<dim3(32, 32), 256>>>(W_pos, 1024, 1024);
    k_split <<<1024*1024/1024, 256>>>(pos_emb, 1024*1024);
    k_gemm_main<<<dim3(8, 8), 256, SM_BYTES>>>(1024, 1024);
    k_reshape_r<<<1024*1024/1024, 256>>>(b_pos);

    // P = (q+v) @ r^T per (b,h)
    k_gemm_pos<<<dim3(8, 4, 128), 256, SM_BYTES>>>();

    // attention
    k_attn<<<dim3(8, 128), 256, 86016>>>();

    // output projection
    k_split_av<<<4096*1024/1024, 256>>>();
    k_tsplit<<<dim3(32, 32), 256>>>(W_proj, 1024, 1024);
    k_gemm_main<<<dim3(8, 32), 256, SM_BYTES>>>(1024, 1024);
    k_biasout<<<4096*1024/1024, 256>>>(b_proj, out);
}

// round 5
// speedup vs baseline: 2.7329x; 1.7990x over previous
#include <cuda_runtime.h>
#include <cuda_bf16.h>
#include <stdint.h>

#define CUR   512
#define FULLL 1024
#define BSZ   8
#define DIMM  1024
#define NH    16
#define HD    64

// ---------------- scratch (device globals; allocation-free) ----------------
__device__ __nv_bfloat16 g_QUh[BSZ*NH*CUR*HD], g_QUl[BSZ*NH*CUR*HD];
__device__ __nv_bfloat16 g_QVh[BSZ*NH*CUR*HD], g_QVl[BSZ*NH*CUR*HD];
__device__ __nv_bfloat16 g_Kh [BSZ*NH*FULLL*HD], g_Kl [BSZ*NH*FULLL*HD];
__device__ __nv_bfloat16 g_Vh [BSZ*NH*FULLL*HD], g_Vl [BSZ*NH*FULLL*HD];
__device__ __nv_bfloat16 g_Rh [NH*FULLL*HD],   g_Rl [NH*FULLL*HD];
__device__ float g_P [(size_t)BSZ*NH*CUR*FULLL];
__device__ __nv_bfloat16 g_Ah[8192*1024], g_Al[8192*1024];   // A operand (split)
__device__ __nv_bfloat16 g_Wh[2048*1024], g_Wl[2048*1024];   // B operand (W^T split)
__device__ float g_C[(size_t)8192*2048];                     // GEMM output

// ---------------- helpers ----------------
__device__ __forceinline__ uint32_t smem_u32(const void* p){
    uint32_t a; asm("{ .reg .u64 t; cvta.to.shared.u64 t, %1; cvt.u32.u64 %0, t; }":"=r"(a):"l"(p)); return a;
}
__device__ __forceinline__ void ldsm4(uint32_t* r, uint32_t addr){
    asm volatile("ldmatrix.sync.aligned.m8n8.x4.shared.b16 {%0,%1,%2,%3}, [%4];"
        : "=r"(r[0]),"=r"(r[1]),"=r"(r[2]),"=r"(r[3]) : "r"(addr));
}
__device__ __forceinline__ void ldsm4t(uint32_t* r, uint32_t addr){
    asm volatile("ldmatrix.sync.aligned.m8n8.x4.trans.shared.b16 {%0,%1,%2,%3}, [%4];"
        : "=r"(r[0]),"=r"(r[1]),"=r"(r[2]),"=r"(r[3]) : "r"(addr));
}
__device__ __forceinline__ void mma_bf16(float* c, const uint32_t* a, uint32_t b0, uint32_t b1){
    asm volatile("mma.sync.aligned.m16n8k16.row.col.f32.bf16.bf16.f32 "
        "{%0,%1,%2,%3}, {%4,%5,%6,%7}, {%8,%9}, {%0,%1,%2,%3};"
        : "+f"(c[0]),"+f"(c[1]),"+f"(c[2]),"+f"(c[3])
        : "r"(a[0]),"r"(a[1]),"r"(a[2]),"r"(a[3]), "r"(b0),"r"(b1));
}
__device__ __forceinline__ void bfsplit(float x, __nv_bfloat16& h, __nv_bfloat16& l){
    h = __float2bfloat16(x);
    l = __float2bfloat16(x - __bfloat162float(h));
}
__device__ __forceinline__ void split2(float x, float y, uint32_t& hi, uint32_t& lo){
    __nv_bfloat162 hv = __floats2bfloat162_rn(x, y);
    hi = *(uint32_t*)&hv;
    __nv_bfloat162 lv = __floats2bfloat162_rn(x - __bfloat162float(hv.x),
                                              y - __bfloat162float(hv.y));
    lo = *(uint32_t*)&lv;
}

// ---------------- warp-MMA bf16x3 GEMM core (validated round 3) ----------------
#define TSTR 72
#define TILE_ELEMS (128*TSTR)
#define SM_BYTES (4*TILE_ELEMS*2)

__device__ __forceinline__ void load_tile(__nv_bfloat16* dst, const __nv_bfloat16* src, int ld){
    const int tid = threadIdx.x;
    #pragma unroll
    for (int i = 0; i < 4; i++) {
        int s = tid + (i<<8);
        int row = s >> 3, cq = s & 7;
        *(float4*)(dst + row*TSTR + cq*8) = *(const float4*)(src + (size_t)row*ld + cq*8);
    }
}

__device__ void gemm_core(const __nv_bfloat16* Ah, const __nv_bfloat16* Al,
                          const __nv_bfloat16* Bh, const __nv_bfloat16* Bl,
                          float* C, int K, int ldc, int m0, int n0)
{
    extern __shared__ __nv_bfloat16 smb[];
    __nv_bfloat16* sAh = smb;
    __nv_bfloat16* sAl = smb + TILE_ELEMS;
    __nv_bfloat16* sBh = smb + 2*TILE_ELEMS;
    __nv_bfloat16* sBl = smb + 3*TILE_ELEMS;
    const uint32_t bAh = smem_u32(sAh), bAl = smem_u32(sAl);
    const uint32_t bBh = smem_u32(sBh), bBl = smem_u32(sBl);

    const int tid = threadIdx.x;
    const int lane = tid & 31, wid = tid >> 5;
    const int wm = wid >> 2, wn = wid & 3;
    const int g = lane >> 3, lr = lane & 7;

    const int arow = wm*64 + lr + (g & 1)*8;
    const int kcol = (g >> 1)*8;
    uint32_t aoff[4];
    #pragma unroll
    for (int mf = 0; mf < 4; mf++) aoff[mf] = (uint32_t)(((arow + mf*16)*TSTR + kcol)*2);
    const int brow = wn*32 + lr + (g & 1)*8;
    uint32_t boff[2];
    #pragma unroll
    for (int np = 0; np < 2; np++) boff[np] = (uint32_t)(((brow + np*16)*TSTR + kcol)*2);

    float acc[4][4][4] = {};

    const __nv_bfloat16* pAh = Ah + (size_t)m0 * K;
    const __nv_bfloat16* pAl = Al + (size_t)m0 * K;
    const __nv_bfloat16* pBh = Bh + (size_t)n0 * K;
    const __nv_bfloat16* pBl = Bl + (size_t)n0 * K;

    const int nchunk = K >> 6;
    for (int kc = 0; kc < nchunk; kc++) {
        const int k0 = kc << 6;
        __syncthreads();
        load_tile(sAh, pAh + k0, K);
        load_tile(sAl, pAl + k0, K);
        load_tile(sBh, pBh + k0, K);
        load_tile(sBl, pBl + k0, K);
        __syncthreads();
        #pragma unroll
        for (int ks = 0; ks < 4; ks++) {
            const uint32_t kb = ks*32;
            uint32_t ah[4][4], al[4][4], bp[2][4];
            #pragma unroll
            for (int mf = 0; mf < 4; mf++) {
                ldsm4(ah[mf], bAh + aoff[mf] + kb);
                ldsm4(al[mf], bAl + aoff[mf] + kb);
            }
            ldsm4(bp[0], bBh + boff[0] + kb);
            ldsm4(bp[1], bBh + boff[1] + kb);
            #pragma unroll
            for (int mf = 0; mf < 4; mf++)
                #pragma unroll
                for (int nf = 0; nf < 4; nf++)
                    mma_bf16(acc[mf][nf], ah[mf], bp[nf>>1][nf&1], bp[nf>>1][2+(nf&1)]);
            #pragma unroll
            for (int mf = 0; mf < 4; mf++)
                #pragma unroll
                for (int nf = 0; nf < 4; nf++)
                    mma_bf16(acc[mf][nf], al[mf], bp[nf>>1][nf&1], bp[nf>>1][2+(nf&1)]);
            ldsm4(bp[0], bBl + boff[0] + kb);
            ldsm4(bp[1], bBl + boff[1] + kb);
            #pragma unroll
            for (int mf = 0; mf < 4; mf++)
                #pragma unroll
                for (int nf = 0; nf < 4; nf++)
                    mma_bf16(acc[mf][nf], ah[mf], bp[nf>>1][nf&1], bp[nf>>1][2+(nf&1)]);
        }
    }

    const int r0 = m0 + wm*64 + (lane >> 2);
    const int c0 = n0 + wn*32 + (lane & 3)*2;
    #pragma unroll
    for (int mf = 0; mf < 4; mf++)
        #pragma unroll
        for (int nf = 0; nf < 4; nf++) {
            float* p = C + (size_t)(r0 + mf*16)*ldc + c0 + nf*8;
            *(float2*)p           = make_float2(acc[mf][nf][0], acc[mf][nf][1]);
            *(float2*)(p + 8*ldc) = make_float2(acc[mf][nf][2], acc[mf][nf][3]);
        }
}

__global__ __launch_bounds__(256, 2) void k_gemm_main(int K, int ldc) {
    gemm_core(g_Ah, g_Al, g_Wh, g_Wl, g_C, K, ldc, blockIdx.y*128, blockIdx.x*128);
}
__global__ __launch_bounds__(256, 2) void k_gemm_pos() {
    int bh = blockIdx.z, h = bh & 15;
    gemm_core(g_QVh + (size_t)bh*CUR*HD, g_QVl + (size_t)bh*CUR*HD,
              g_Rh  + (size_t)h*FULLL*HD, g_Rl + (size_t)h*FULLL*HD,
              g_P   + (size_t)bh*CUR*FULLL, HD, FULLL, blockIdx.y*128, blockIdx.x*128);
}

// ---------------- conversion / reshape kernels ----------------
__global__ __launch_bounds__(256) void k_split(const float* __restrict__ src, int n){
    int i = (blockIdx.x*256 + threadIdx.x) * 4;
    if (i >= n) return;
    float4 v = *(const float4*)(src + i);
    __nv_bfloat16 h, l;
    bfsplit(v.x, h, l); g_Ah[i+0]=h; g_Al[i+0]=l;
    bfsplit(v.y, h, l); g_Ah[i+1]=h; g_Al[i+1]=l;
    bfsplit(v.z, h, l); g_Ah[i+2]=h; g_Al[i+2]=l;
    bfsplit(v.w, h, l); g_Ah[i+3]=h; g_Al[i+3]=l;
}
// W [K][N] fp32 -> g_Wh/g_Wl [N][K] bf16
__global__ __launch_bounds__(256) void k_tsplit(const float* __restrict__ W, int K, int N){
    __shared__ float t[32][33];
    int k0 = blockIdx.y*32, n0 = blockIdx.x*32;
    int tx = threadIdx.x & 31, ty = threadIdx.x >> 5;
    #pragma unroll
    for (int i = 0; i < 32; i += 8)
        t[ty+i][tx] = W[(size_t)(k0+ty+i)*N + n0+tx];
    __syncthreads();
    #pragma unroll
    for (int i = 0; i < 32; i += 8) {
        float v = t[tx][ty+i];
        __nv_bfloat16 h, l; bfsplit(v, h, l);
        size_t o = (size_t)(n0+ty+i)*K + k0+tx;
        g_Wh[o] = h; g_Wl[o] = l;
    }
}
__global__ __launch_bounds__(256) void k_reshape_kv(const float* __restrict__ bias){
    size_t i = ((size_t)blockIdx.x*256 + threadIdx.x) * 4;
    int m = (int)(i >> 11), n = (int)(i & 2047);
    int f = m >> 3, b = m & 7;
    bool isK = n < 1024;
    int nn = isK ? n : n - 1024;
    int h = nn >> 6, d = nn & 63;
    float4 v = *(const float4*)(g_C + i);
    v.x += bias[n]; v.y += bias[n+1]; v.z += bias[n+2]; v.w += bias[n+3];
    __nv_bfloat16* Dh = isK ? g_Kh : g_Vh;
    __nv_bfloat16* Dl = isK ? g_Kl : g_Vl;
    size_t o = (((size_t)(b*NH + h)*FULLL) + f)*HD + d;
    uint32_t h0,l0,h1,l1;
    split2(v.x, v.y, h0, l0);
    split2(v.z, v.w, h1, l1);
    *(uint32_t*)(Dh + o)     = h0; *(uint32_t*)(Dh + o + 2) = h1;
    *(uint32_t*)(Dl + o)     = l0; *(uint32_t*)(Dl + o + 2) = l1;
}
__global__ __launch_bounds__(256) void k_reshape_q(const float* __restrict__ bias,
                                                   const float* __restrict__ u,
                                                   const float* __restrict__ v){
    size_t i = ((size_t)blockIdx.x*256 + threadIdx.x) * 4;
    int m = (int)(i >> 10), n = (int)(i & 1023);
    int c = m >> 3, b = m & 7;
    int h = n >> 6, d = n & 63;
    float4 q = *(const float4*)(g_C + i);
    q.x += bias[n]; q.y += bias[n+1]; q.z += bias[n+2]; q.w += bias[n+3];
    size_t o = (((size_t)(b*NH + h)*CUR) + c)*HD + d;
    uint32_t h0,l0,h1,l1;
    split2(q.x+u[n], q.y+u[n+1], h0, l0);
    split2(q.z+u[n+2], q.w+u[n+3], h1, l1);
    *(uint32_t*)(g_QUh + o) = h0; *(uint32_t*)(g_QUh + o + 2) = h1;
    *(uint32_t*)(g_QUl + o) = l0; *(uint32_t*)(g_QUl + o + 2) = l1;
    split2(q.x+v[n], q.y+v[n+1], h0, l0);
    split2(q.z+v[n+2], q.w+v[n+3], h1, l1);
    *(uint32_t*)(g_QVh + o) = h0; *(uint32_t*)(g_QVh + o + 2) = h1;
    *(uint32_t*)(g_QVl + o) = l0; *(uint32_t*)(g_QVl + o + 2) = l1;
}
__global__ __launch_bounds__(256) void k_reshape_r(const float* __restrict__ bias){
    size_t i = ((size_t)blockIdx.x*256 + threadIdx.x) * 4;
    int t = (int)(i >> 10), n = (int)(i & 1023);
    int h = n >> 6, d = n & 63;
    float4 q = *(const float4*)(g_C + i);
    q.x += bias[n]; q.y += bias[n+1]; q.z += bias[n+2]; q.w += bias[n+3];
    size_t o = ((size_t)h*FULLL + t)*HD + d;
    uint32_t h0,l0,h1,l1;
    split2(q.x, q.y, h0, l0);
    split2(q.z, q.w, h1, l1);
    *(uint32_t*)(g_Rh + o) = h0; *(uint32_t*)(g_Rh + o + 2) = h1;
    *(uint32_t*)(g_Rl + o) = l0; *(uint32_t*)(g_Rl + o + 2) = l1;
}
__global__ __launch_bounds__(256) void k_biasout(const float* __restrict__ bias, float* __restrict__ out){
    size_t i = ((size_t)blockIdx.x*256 + threadIdx.x) * 4;
    int n = (int)(i & 1023);
    float4 q = *(const float4*)(g_C + i);
    *(float4*)(out + i) = make_float4(q.x+bias[n], q.y+bias[n+1], q.z+bias[n+2], q.w+bias[n+3]);
}

// ---------------- tensor-core flash attention ----------------
#define ARS 72
#define AT_BYTES (4*64*ARS*2)

__global__ __launch_bounds__(256) void k_attn_mma()
{
    const int bh = blockIdx.y, b = bh >> 4, h = bh & 15;
    const int a0 = blockIdx.x * 128;
    extern __shared__ __nv_bfloat16 smb[];
    __nv_bfloat16* sKh = smb;
    __nv_bfloat16* sKl = smb + 64*ARS;
    __nv_bfloat16* sVh = smb + 2*64*ARS;
    __nv_bfloat16* sVl = smb + 3*64*ARS;
    const uint32_t bKh = smem_u32(sKh), bKl = smem_u32(sKl);
    const uint32_t bVh = smem_u32(sVh), bVl = smem_u32(sVl);
    const uint32_t bQ  = bKh;

    const int tid = threadIdx.x, lane = tid & 31, w = tid >> 5;
    const int g = lane >> 2, q = lane & 3, qq2 = q*2;
    const int lr = lane & 7, gb = lane >> 3;
    const uint32_t lof = (uint32_t)((lr + (gb & 1)*8)*(ARS*2) + (gb >> 1)*16);

    // ---- stage QU hi/lo -> register A fragments ----
    const __nv_bfloat16* Qh = g_QUh + ((size_t)bh*CUR + a0)*HD;
    const __nv_bfloat16* Ql = g_QUl + ((size_t)bh*CUR + a0)*HD;
    uint32_t aQh[4][4], aQl[4][4];
    #pragma unroll
    for (int i = 0; i < 4; i++) {
        int s = tid + (i<<8); int row = s >> 3, c = s & 7;
        *(float4*)(smb + row*ARS + c*8) = *(const float4*)(Qh + row*HD + c*8);
    }
    __syncthreads();
    #pragma unroll
    for (int ks = 0; ks < 4; ks++) ldsm4(aQh[ks], bQ + (uint32_t)(w*16*ARS*2) + lof + ks*32);
    __syncthreads();
    #pragma unroll
    for (int i = 0; i < 4; i++) {
        int s = tid + (i<<8); int row = s >> 3, c = s & 7;
        *(float4*)(smb + row*ARS + c*8) = *(const float4*)(Ql + row*HD + c*8);
    }
    __syncthreads();
    #pragma unroll
    for (int ks = 0; ks < 4; ks++) ldsm4(aQl[ks], bQ + (uint32_t)(w*16*ARS*2) + lof + ks*32);

    float oacc[8][4] = {};
    float rm0 = -1e30f, rm1 = -1e30f, rl0 = 0.f, rl1 = 0.f;
    const int arow0 = a0 + w*16 + g;
    const float* P0 = g_P + ((size_t)bh*CUR + arow0)*FULLL;
    const float* P1 = P0 + 8*FULLL;
    const int amax = a0 + w*16 + 15;
    const int nkb = (a0 + 640) >> 6;
    const __nv_bfloat16* Kh = g_Kh + (size_t)bh*FULLL*HD;
    const __nv_bfloat16* Kl = g_Kl + (size_t)bh*FULLL*HD;
    const __nv_bfloat16* Vh = g_Vh + (size_t)bh*FULLL*HD;
    const __nv_bfloat16* Vl = g_Vl + (size_t)bh*FULLL*HD;
    const float CS = 0.125f * 1.44269504f;

    for (int kb = 0; kb < nkb; kb++) {
        const int j0 = kb << 6;
        __syncthreads();
        #pragma unroll
        for (int i = 0; i < 2; i++) {
            int s = tid + (i<<8); int row = s >> 3, c = s & 7;
            int off = row*ARS + c*8;
            size_t gi = (size_t)(j0 + row)*HD + c*8;
            *(float4*)(sKh + off) = *(const float4*)(Kh + gi);
            *(float4*)(sKl + off) = *(const float4*)(Kl + gi);
            *(float4*)(sVh + off) = *(const float4*)(Vh + gi);
            *(float4*)(sVl + off) = *(const float4*)(Vl + gi);
        }
        __syncthreads();
        if (j0 > amax + 512) continue;

        // ---- S = QU @ K^T (3-term split) ----
        float sacc[8][4] = {};
        #pragma unroll
        for (int n16 = 0; n16 < 4; n16++) {
            #pragma unroll
            for (int ks = 0; ks < 4; ks++) {
                uint32_t kh4[4], kl4[4];
                ldsm4(kh4, bKh + (uint32_t)(n16*16*ARS*2) + lof + ks*32);
                ldsm4(kl4, bKl + (uint32_t)(n16*16*ARS*2) + lof + ks*32);
                mma_bf16(sacc[2*n16],   aQh[ks], kh4[0], kh4[2]);
                mma_bf16(sacc[2*n16+1], aQh[ks], kh4[1], kh4[3]);
                mma_bf16(sacc[2*n16],   aQh[ks], kl4[0], kl4[2]);
                mma_bf16(sacc[2*n16+1], aQh[ks], kl4[1], kl4[3]);
                mma_bf16(sacc[2*n16],   aQl[ks], kh4[0], kh4[2]);
                mma_bf16(sacc[2*n16+1], aQl[ks], kh4[1], kh4[3]);
            }
        }

        // ---- add rel-shifted position scores, scale, mask ----
        #pragma unroll
        for (int nf = 0; nf < 8; nf++) {
            int j = j0 + nf*8 + qq2;
            int m0 = j + (CUR - 1) - arow0;
            int m1 = m0 - 8;
            sacc[nf][0] = (m0     < FULLL) ? (sacc[nf][0] + P0[m0])   * CS : -1e30f;
            sacc[nf][1] = (m0 + 1 < FULLL) ? (sacc[nf][1] + P0[m0+1]) * CS : -1e30f;
            sacc[nf][2] = (m1     < FULLL) ? (sacc[nf][2] + P1[m1])   * CS : -1e30f;
            sacc[nf][3] = (m1 + 1 < FULLL) ? (sacc[nf][3] + P1[m1+1]) * CS : -1e30f;
        }

        // ---- online softmax ----
        float mx0 = -1e30f, mx1 = -1e30f;
        #pragma unroll
        for (int nf = 0; nf < 8; nf++) {
            mx0 = fmaxf(mx0, fmaxf(sacc[nf][0], sacc[nf][1]));
            mx1 = fmaxf(mx1, fmaxf(sacc[nf][2], sacc[nf][3]));
        }
        mx0 = fmaxf(mx0, __shfl_xor_sync(0xffffffffu, mx0, 1));
        mx0 = fmaxf(mx0, __shfl_xor_sync(0xffffffffu, mx0, 2));
        mx1 = fmaxf(mx1, __shfl_xor_sync(0xffffffffu, mx1, 1));
        mx1 = fmaxf(mx1, __shfl_xor_sync(0xffffffffu, mx1, 2));
        float mn0 = fmaxf(rm0, mx0), mn1 = fmaxf(rm1, mx1);
        float cr0 = exp2f(rm0 - mn0), cr1 = exp2f(rm1 - mn1);
        rm0 = mn0; rm1 = mn1;
        float ls0 = 0.f, ls1 = 0.f;
        #pragma unroll
        for (int nf = 0; nf < 8; nf++) {
            float p0 = exp2f(sacc[nf][0] - mn0); sacc[nf][0] = p0; ls0 += p0;
            float p1 = exp2f(sacc[nf][1] - mn0); sacc[nf][1] = p1; ls0 += p1;
            float p2 = exp2f(sacc[nf][2] - mn1); sacc[nf][2] = p2; ls1 += p2;
            float p3 = exp2f(sacc[nf][3] - mn1); sacc[nf][3] = p3; ls1 += p3;
        }
        rl0 = rl0*cr0 + ls0; rl1 = rl1*cr1 + ls1;
        #pragma unroll
        for (int nf = 0; nf < 8; nf++) {
            oacc[nf][0] *= cr0; oacc[nf][1] *= cr0;
            oacc[nf][2] *= cr1; oacc[nf][3] *= cr1;
        }

        // ---- O += P~ @ V (probs split + V split, 3-term) ----
        // trans-load pairing: m0=(k0-7,n0-7) m1=(k8-15,n0-7) m2=(k0-7,n8-15) m3=(k8-15,n8-15)
        #pragma unroll
        for (int kf = 0; kf < 4; kf++) {
            uint32_t aph[4], apl[4];
            split2(sacc[2*kf][0],   sacc[2*kf][1],   aph[0], apl[0]);
            split2(sacc[2*kf][2],   sacc[2*kf][3],   aph[1], apl[1]);
            split2(sacc[2*kf+1][0], sacc[2*kf+1][1], aph[2], apl[2]);
            split2(sacc[2*kf+1][2], sacc[2*kf+1][3], aph[3], apl[3]);
            #pragma unroll
            for (int d16 = 0; d16 < 4; d16++) {
                uint32_t vh4[4], vl4[4];
                ldsm4t(vh4, bVh + (uint32_t)(kf*16*ARS*2) + lof + d16*32);
                ldsm4t(vl4, bVl + (uint32_t)(kf*16*ARS*2) + lof + d16*32);
                mma_bf16(oacc[2*d16],   aph, vh4[0], vh4[1]);
                mma_bf16(oacc[2*d16+1], aph, vh4[2], vh4[3]);
                mma_bf16(oacc[2*d16],   aph, vl4[0], vl4[1]);
                mma_bf16(oacc[2*d16+1], aph, vl4[2], vl4[3]);
                mma_bf16(oacc[2*d16],   apl, vh4[0], vh4[1]);
                mma_bf16(oacc[2*d16+1], apl, vh4[2], vh4[3]);
            }
        }
    }

    // ---- finalize ----
    rl0 += __shfl_xor_sync(0xffffffffu, rl0, 1);
    rl0 += __shfl_xor_sync(0xffffffffu, rl0, 2);
    rl1 += __shfl_xor_sync(0xffffffffu, rl1, 1);
    rl1 += __shfl_xor_sync(0xffffffffu, rl1, 2);
    float i0 = 1.f / rl0, i1 = 1.f / rl1;
    size_t base0 = ((size_t)arow0*BSZ + b)*(NH*HD) + h*HD;
    size_t base1 = ((size_t)(arow0+8)*BSZ + b)*(NH*HD) + h*HD;
    #pragma unroll
    for (int nf = 0; nf < 8; nf++) {
        int d = nf*8 + qq2;
        uint32_t hi, lo;
        split2(oacc[nf][0]*i0, oacc[nf][1]*i0, hi, lo);
        *(uint32_t*)(g_Ah + base0 + d) = hi;
        *(uint32_t*)(g_Al + base0 + d) = lo;
        split2(oacc[nf][2]*i1, oacc[nf][3]*i1, hi, lo);
        *(uint32_t*)(g_Ah + base1 + d) = hi;
        *(uint32_t*)(g_Al + base1 + d) = lo;
    }
}

// ---------------- launch ----------------
extern "C" void kernel_launch(void* const* d_in, const int* in_sizes, int n_in,
                              void* d_out, int out_size)
{
    const float* inputs     = (const float*)d_in[0];
    const float* pos_emb    = (const float*)d_in[1];
    const float* full_input = (const float*)d_in[2];
    const float* u          = (const float*)d_in[3];
    const float* v          = (const float*)d_in[4];
    // d_in[5] = mask: unused (derived analytically)
    const float* W_kv   = (const float*)d_in[6];
    const float* b_kv   = (const float*)d_in[7];
    const float* W_q    = (const float*)d_in[8];
    const float* b_q    = (const float*)d_in[9];
    const float* W_pos  = (const float*)d_in[10];
    const float* b_pos  = (const float*)d_in[11];
    const float* W_proj = (const float*)d_in[12];
    const float* b_proj = (const float*)d_in[13];
    float* out = (float*)d_out;

    cudaFuncSetAttribute(k_gemm_main, cudaFuncAttributeMaxDynamicSharedMemorySize, SM_BYTES);
    cudaFuncSetAttribute(k_gemm_pos,  cudaFuncAttributeMaxDynamicSharedMemorySize, SM_BYTES);

    // KV projection
    k_tsplit<<<dim3(2048/32, 1024/32), 256>>>(W_kv, 1024, 2048);
    k_split <<<8192*1024/1024, 256>>>(full_input, 8192*1024);
    k_gemm_main<<<dim3(16, 64), 256, SM_BYTES>>>(1024, 2048);
    k_reshape_kv<<<8192*2048/1024, 256>>>(b_kv);

    // Q projection
    k_tsplit<<<dim3(32, 32), 256>>>(W_q, 1024, 1024);
    k_split <<<4096*1024/1024, 256>>>(inputs, 4096*1024);
    k_gemm_main<<<dim3(8, 32), 256, SM_BYTES>>>(1024, 1024);
    k_reshape_q<<<4096*1024/1024, 256>>>(b_q, u, v);

    // R projection
    k_tsplit<<<dim3(32, 32), 256>>>(W_pos, 1024, 1024);
    k_split <<<1024*1024/1024, 256>>>(pos_emb, 1024*1024);
    k_gemm_main<<<dim3(8, 8), 256, SM_BYTES>>>(1024, 1024);
    k_reshape_r<<<1024*1024/1024, 256>>>(b_pos);

    // P = (q+v) @ r^T per (b,h)
    k_gemm_pos<<<dim3(8, 4, 128), 256, SM_BYTES>>>();

    // attention (tensor-core flash, writes proj A operand directly)
    k_attn_mma<<<dim3(4, 128), 256, AT_BYTES>>>();

    // output projection
    k_tsplit<<<dim3(32, 32), 256>>>(W_proj, 1024, 1024);
    k_gemm_main<<<dim3(8, 32), 256, SM_BYTES>>>(1024, 1024);
    k_biasout<<<4096*1024/1024, 256>>>(b_proj, out);
}

// round 6
// speedup vs baseline: 2.8058x; 1.0267x over previous
#include <cuda_runtime.h>
#include <cuda_bf16.h>
#include <stdint.h>

#define CUR   512
#define FULLL 1024
#define BSZ   8
#define DIMM  1024
#define NH    16
#define HD    64

// ---------------- scratch (device globals; allocation-free) ----------------
__device__ __nv_bfloat16 g_QUh[BSZ*NH*CUR*HD], g_QUl[BSZ*NH*CUR*HD];
__device__ __nv_bfloat16 g_QVh[BSZ*NH*CUR*HD], g_QVl[BSZ*NH*CUR*HD];
__device__ __nv_bfloat16 g_Kh [BSZ*NH*FULLL*HD], g_Kl [BSZ*NH*FULLL*HD];
__device__ __nv_bfloat16 g_Vh [BSZ*NH*FULLL*HD], g_Vl [BSZ*NH*FULLL*HD];
__device__ __nv_bfloat16 g_Rh [NH*FULLL*HD],   g_Rl [NH*FULLL*HD];
__device__ float g_P [(size_t)BSZ*NH*CUR*FULLL];
__device__ __nv_bfloat16 g_Ah[8192*1024], g_Al[8192*1024];   // A operand (split)
__device__ __nv_bfloat16 g_Wh[2048*1024], g_Wl[2048*1024];   // B operand (W^T split)

// ---------------- helpers ----------------
__device__ __forceinline__ uint32_t smem_u32(const void* p){
    uint32_t a; asm("{ .reg .u64 t; cvta.to.shared.u64 t, %1; cvt.u32.u64 %0, t; }":"=r"(a):"l"(p)); return a;
}
__device__ __forceinline__ void ldsm4(uint32_t* r, uint32_t addr){
    asm volatile("ldmatrix.sync.aligned.m8n8.x4.shared.b16 {%0,%1,%2,%3}, [%4];"
        : "=r"(r[0]),"=r"(r[1]),"=r"(r[2]),"=r"(r[3]) : "r"(addr));
}
__device__ __forceinline__ void ldsm4t(uint32_t* r, uint32_t addr){
    asm volatile("ldmatrix.sync.aligned.m8n8.x4.trans.shared.b16 {%0,%1,%2,%3}, [%4];"
        : "=r"(r[0]),"=r"(r[1]),"=r"(r[2]),"=r"(r[3]) : "r"(addr));
}
__device__ __forceinline__ void mma_bf16(float* c, const uint32_t* a, uint32_t b0, uint32_t b1){
    asm volatile("mma.sync.aligned.m16n8k16.row.col.f32.bf16.bf16.f32 "
        "{%0,%1,%2,%3}, {%4,%5,%6,%7}, {%8,%9}, {%0,%1,%2,%3};"
        : "+f"(c[0]),"+f"(c[1]),"+f"(c[2]),"+f"(c[3])
        : "r"(a[0]),"r"(a[1]),"r"(a[2]),"r"(a[3]), "r"(b0),"r"(b1));
}
__device__ __forceinline__ void bfsplit(float x, __nv_bfloat16& h, __nv_bfloat16& l){
    h = __float2bfloat16(x);
    l = __float2bfloat16(x - __bfloat162float(h));
}
__device__ __forceinline__ void split2(float x, float y, uint32_t& hi, uint32_t& lo){
    __nv_bfloat162 hv = __floats2bfloat162_rn(x, y);
    hi = *(uint32_t*)&hv;
    __nv_bfloat162 lv = __floats2bfloat162_rn(x - __bfloat162float(hv.x),
                                              y - __bfloat162float(hv.y));
    lo = *(uint32_t*)&lv;
}
__device__ __forceinline__ void cpasync16(uint32_t dst, const void* src){
    asm volatile("cp.async.cg.shared.global [%0], [%1], 16;" :: "r"(dst), "l"(src));
}

// ---------------- warp-MMA bf16x3 GEMM compute core ----------------
#define TSTR 72
#define TILE_ELEMS (128*TSTR)
#define SM_BYTES (4*TILE_ELEMS*2)

__device__ __forceinline__ void load_tile_async(uint32_t dsm, const __nv_bfloat16* src, int ld){
    const int tid = threadIdx.x;
    #pragma unroll
    for (int i = 0; i < 4; i++) {
        int s = tid + (i<<8);
        int row = s >> 3, cq = s & 7;
        cpasync16(dsm + (uint32_t)(row*TSTR + cq*8)*2, src + (size_t)row*ld + cq*8);
    }
}

// computes acc[4][4][4]: rows r0=wm*64+(lane>>2)+mf*16 (+8 for c2/c3),
// cols c0=wn*32+(lane&3)*2+nf*8 (within 128x128 tile)
__device__ __forceinline__ void gemm_compute(
    const __nv_bfloat16* pAh, const __nv_bfloat16* pAl,
    const __nv_bfloat16* pBh, const __nv_bfloat16* pBl,
    int K, float acc[4][4][4])
{
    extern __shared__ __nv_bfloat16 smb[];
    const uint32_t bAh = smem_u32(smb);
    const uint32_t bAl = bAh + TILE_ELEMS*2;
    const uint32_t bBh = bAh + 2*TILE_ELEMS*2;
    const uint32_t bBl = bAh + 3*TILE_ELEMS*2;

    const int lane = threadIdx.x & 31, wid = threadIdx.x >> 5;
    const int wm = wid >> 2, wn = wid & 3;
    const int g = lane >> 3, lr = lane & 7;

    const int arow = wm*64 + lr + (g & 1)*8;
    const int kcol = (g >> 1)*8;
    uint32_t aoff[4];
    #pragma unroll
    for (int mf = 0; mf < 4; mf++) aoff[mf] = (uint32_t)(((arow + mf*16)*TSTR + kcol)*2);
    const int brow = wn*32 + lr + (g & 1)*8;
    uint32_t boff[2];
    #pragma unroll
    for (int np = 0; np < 2; np++) boff[np] = (uint32_t)(((brow + np*16)*TSTR + kcol)*2);

    const int nchunk = K >> 6;
    for (int kc = 0; kc < nchunk; kc++) {
        const int k0 = kc << 6;
        __syncthreads();
        load_tile_async(bAh, pAh + k0, K);
        load_tile_async(bAl, pAl + k0, K);
        load_tile_async(bBh, pBh + k0, K);
        load_tile_async(bBl, pBl + k0, K);
        asm volatile("cp.async.commit_group;");
        asm volatile("cp.async.wait_group 0;" ::: "memory");
        __syncthreads();
        #pragma unroll
        for (int ks = 0; ks < 4; ks++) {
            const uint32_t kb = ks*32;
            uint32_t ah[4][4], al[4][4], bp[2][4];
            #pragma unroll
            for (int mf = 0; mf < 4; mf++) {
                ldsm4(ah[mf], bAh + aoff[mf] + kb);
                ldsm4(al[mf], bAl + aoff[mf] + kb);
            }
            ldsm4(bp[0], bBh + boff[0] + kb);
            ldsm4(bp[1], bBh + boff[1] + kb);
            #pragma unroll
            for (int mf = 0; mf < 4; mf++)
                #pragma unroll
                for (int nf = 0; nf < 4; nf++)
                    mma_bf16(acc[mf][nf], ah[mf], bp[nf>>1][nf&1], bp[nf>>1][2+(nf&1)]);
            #pragma unroll
            for (int mf = 0; mf < 4; mf++)
                #pragma unroll
                for (int nf = 0; nf < 4; nf++)
                    mma_bf16(acc[mf][nf], al[mf], bp[nf>>1][nf&1], bp[nf>>1][2+(nf&1)]);
            ldsm4(bp[0], bBl + boff[0] + kb);
            ldsm4(bp[1], bBl + boff[1] + kb);
            #pragma unroll
            for (int mf = 0; mf < 4; mf++)
                #pragma unroll
                for (int nf = 0; nf < 4; nf++)
                    mma_bf16(acc[mf][nf], ah[mf], bp[nf>>1][nf&1], bp[nf>>1][2+(nf&1)]);
        }
    }
}

// ---------------- GEMM wrappers with fused epilogues ----------------
// KV: A=g_Ah/g_Al (full_input split), B=g_Wh/g_Wl (W_kv^T), N=2048.
// out: split bf16 K/V in [b][h][f][d]
__global__ __launch_bounds__(256, 2) void k_gemm_kv(const float* __restrict__ bias)
{
    const int m0 = blockIdx.y*128, n0 = blockIdx.x*128;
    float acc[4][4][4] = {};
    gemm_compute(g_Ah + (size_t)m0*DIMM, g_Al + (size_t)m0*DIMM,
                 g_Wh + (size_t)n0*DIMM, g_Wl + (size_t)n0*DIMM, DIMM, acc);
    const int lane = threadIdx.x & 31, wid = threadIdx.x >> 5;
    const int r0 = m0 + (wid>>2)*64 + (lane>>2);
    const int c0 = n0 + (wid&3)*32 + (lane&3)*2;
    #pragma unroll
    for (int nf = 0; nf < 4; nf++) {
        const int n = c0 + nf*8;
        const bool isK = n < 1024;
        const int nn = n & 1023, hh = nn >> 6, d = nn & 63;
        __nv_bfloat16* Dh = isK ? g_Kh : g_Vh;
        __nv_bfloat16* Dl = isK ? g_Kl : g_Vl;
        const float2 bv = *(const float2*)(bias + n);
        #pragma unroll
        for (int mf = 0; mf < 4; mf++) {
            int m = r0 + mf*16;
            int f = m >> 3, b = m & 7;
            size_t o = (((size_t)(b*NH + hh)*FULLL) + f)*HD + d;
            uint32_t hi, lo;
            split2(acc[mf][nf][0] + bv.x, acc[mf][nf][1] + bv.y, hi, lo);
            *(uint32_t*)(Dh + o) = hi; *(uint32_t*)(Dl + o) = lo;
            // row m+8 -> f+1 (same b)
            split2(acc[mf][nf][2] + bv.x, acc[mf][nf][3] + bv.y, hi, lo);
            *(uint32_t*)(Dh + o + HD) = hi; *(uint32_t*)(Dl + o + HD) = lo;
        }
    }
}

// Q: A=g_Ah/g_Al (inputs split), B=W_q^T split, N=1024. out: QU/QV split [b][h][c][d]
__global__ __launch_bounds__(256, 2) void k_gemm_q(const float* __restrict__ bias,
                                                   const float* __restrict__ u,
                                                   const float* __restrict__ v)
{
    const int m0 = blockIdx.y*128, n0 = blockIdx.x*128;
    float acc[4][4][4] = {};
    gemm_compute(g_Ah + (size_t)m0*DIMM, g_Al + (size_t)m0*DIMM,
                 g_Wh + (size_t)n0*DIMM, g_Wl + (size_t)n0*DIMM, DIMM, acc);
    const int lane = threadIdx.x & 31, wid = threadIdx.x >> 5;
    const int r0 = m0 + (wid>>2)*64 + (lane>>2);
    const int c0 = n0 + (wid&3)*32 + (lane&3)*2;
    #pragma unroll
    for (int nf = 0; nf < 4; nf++) {
        const int n = c0 + nf*8;
        const int hh = n >> 6, d = n & 63;
        const float2 bv = *(const float2*)(bias + n);
        const float2 uv = *(const float2*)(u + n);
        const float2 vv = *(const float2*)(v + n);
        #pragma unroll
        for (int mf = 0; mf < 4; mf++) {
            int m = r0 + mf*16;
            int c = m >> 3, b = m & 7;
            size_t o = (((size_t)(b*NH + hh)*CUR) + c)*HD + d;
            float x0 = acc[mf][nf][0] + bv.x, x1 = acc[mf][nf][1] + bv.y;
            uint32_t hi, lo;
            split2(x0 + uv.x, x1 + uv.y, hi, lo);
            *(uint32_t*)(g_QUh + o) = hi; *(uint32_t*)(g_QUl + o) = lo;
            split2(x0 + vv.x, x1 + vv.y, hi, lo);
            *(uint32_t*)(g_QVh + o) = hi; *(uint32_t*)(g_QVl + o) = lo;
            // row m+8 -> c+1
            float y0 = acc[mf][nf][2] + bv.x, y1 = acc[mf][nf][3] + bv.y;
            split2(y0 + uv.x, y1 + uv.y, hi, lo);
            *(uint32_t*)(g_QUh + o + HD) = hi; *(uint32_t*)(g_QUl + o + HD) = lo;
            split2(y0 + vv.x, y1 + vv.y, hi, lo);
            *(uint32_t*)(g_QVh + o + HD) = hi; *(uint32_t*)(g_QVl + o + HD) = lo;
        }
    }
}

// R: A = pos_emb split, N=1024. out: Rh/Rl [h][t][d]
__global__ __launch_bounds__(256, 2) void k_gemm_r(const float* __restrict__ bias)
{
    const int m0 = blockIdx.y*128, n0 = blockIdx.x*128;
    float acc[4][4][4] = {};
    gemm_compute(g_Ah + (size_t)m0*DIMM, g_Al + (size_t)m0*DIMM,
                 g_Wh + (size_t)n0*DIMM, g_Wl + (size_t)n0*DIMM, DIMM, acc);
    const int lane = threadIdx.x & 31, wid = threadIdx.x >> 5;
    const int r0 = m0 + (wid>>2)*64 + (lane>>2);
    const int c0 = n0 + (wid&3)*32 + (lane&3)*2;
    #pragma unroll
    for (int nf = 0; nf < 4; nf++) {
        const int n = c0 + nf*8;
        const int hh = n >> 6, d = n & 63;
        const float2 bv = *(const float2*)(bias + n);
        #pragma unroll
        for (int mf = 0; mf < 4; mf++) {
            int t = r0 + mf*16;
            size_t o = ((size_t)hh*FULLL + t)*HD + d;
            uint32_t hi, lo;
            split2(acc[mf][nf][0] + bv.x, acc[mf][nf][1] + bv.y, hi, lo);
            *(uint32_t*)(g_Rh + o) = hi; *(uint32_t*)(g_Rl + o) = lo;
            split2(acc[mf][nf][2] + bv.x, acc[mf][nf][3] + bv.y, hi, lo);
            *(uint32_t*)(g_Rh + o + 8*HD) = hi; *(uint32_t*)(g_Rl + o + 8*HD) = lo;
        }
    }
}

// P = QV @ R^T per (b,h): K=64, writes fp32 g_P
__global__ __launch_bounds__(256, 2) void k_gemm_pos()
{
    const int bh = blockIdx.z, hh = bh & 15;
    const int m0 = blockIdx.y*128, n0 = blockIdx.x*128;
    float acc[4][4][4] = {};
    gemm_compute(g_QVh + ((size_t)bh*CUR + m0)*HD, g_QVl + ((size_t)bh*CUR + m0)*HD,
                 g_Rh  + ((size_t)hh*FULLL + n0)*HD, g_Rl + ((size_t)hh*FULLL + n0)*HD, HD, acc);
    float* Pp = g_P + (size_t)bh*CUR*FULLL;
    const int lane = threadIdx.x & 31, wid = threadIdx.x >> 5;
    const int r0 = m0 + (wid>>2)*64 + (lane>>2);
    const int c0 = n0 + (wid&3)*32 + (lane&3)*2;
    #pragma unroll
    for (int mf = 0; mf < 4; mf++)
        #pragma unroll
        for (int nf = 0; nf < 4; nf++) {
            float* p = Pp + (size_t)(r0 + mf*16)*FULLL + c0 + nf*8;
            *(float2*)p             = make_float2(acc[mf][nf][0], acc[mf][nf][1]);
            *(float2*)(p + 8*FULLL) = make_float2(acc[mf][nf][2], acc[mf][nf][3]);
        }
}

// proj: A = attention output split (g_Ah/g_Al), writes fp32 out + bias
__global__ __launch_bounds__(256, 2) void k_gemm_proj(const float* __restrict__ bias,
                                                      float* __restrict__ out)
{
    const int m0 = blockIdx.y*128, n0 = blockIdx.x*128;
    float acc[4][4][4] = {};
    gemm_compute(g_Ah + (size_t)m0*DIMM, g_Al + (size_t)m0*DIMM,
                 g_Wh + (size_t)n0*DIMM, g_Wl + (size_t)n0*DIMM, DIMM, acc);
    const int lane = threadIdx.x & 31, wid = threadIdx.x >> 5;
    const int r0 = m0 + (wid>>2)*64 + (lane>>2);
    const int c0 = n0 + (wid&3)*32 + (lane&3)*2;
    #pragma unroll
    for (int nf = 0; nf < 4; nf++) {
        const float2 bv = *(const float2*)(bias + c0 + nf*8);
        #pragma unroll
        for (int mf = 0; mf < 4; mf++) {
            float* p = out + (size_t)(r0 + mf*16)*DIMM + c0 + nf*8;
            *(float2*)p            = make_float2(acc[mf][nf][0] + bv.x, acc[mf][nf][1] + bv.y);
            *(float2*)(p + 8*DIMM) = make_float2(acc[mf][nf][2] + bv.x, acc[mf][nf][3] + bv.y);
        }
    }
}

// ---------------- conversion kernels ----------------
__global__ __launch_bounds__(256) void k_split(const float* __restrict__ src, int n){
    int i = (blockIdx.x*256 + threadIdx.x) * 4;
    if (i >= n) return;
    float4 v = *(const float4*)(src + i);
    uint32_t h0,l0,h1,l1;
    split2(v.x, v.y, h0, l0);
    split2(v.z, v.w, h1, l1);
    *(uint32_t*)(g_Ah + i) = h0; *(uint32_t*)(g_Ah + i + 2) = h1;
    *(uint32_t*)(g_Al + i) = l0; *(uint32_t*)(g_Al + i + 2) = l1;
}
// W [K][N] fp32 -> g_Wh/g_Wl [N][K] bf16
__global__ __launch_bounds__(256) void k_tsplit(const float* __restrict__ W, int K, int N){
    __shared__ float t[32][33];
    int k0 = blockIdx.y*32, n0 = blockIdx.x*32;
    int tx = threadIdx.x & 31, ty = threadIdx.x >> 5;
    #pragma unroll
    for (int i = 0; i < 32; i += 8)
        t[ty+i][tx] = W[(size_t)(k0+ty+i)*N + n0+tx];
    __syncthreads();
    #pragma unroll
    for (int i = 0; i < 32; i += 8) {
        float v = t[tx][ty+i];
        __nv_bfloat16 h, l; bfsplit(v, h, l);
        size_t o = (size_t)(n0+ty+i)*K + k0+tx;
        g_Wh[o] = h; g_Wl[o] = l;
    }
}

// ---------------- tensor-core flash attention (validated round 5) ----------------
#define ARS 72
#define AT_BYTES (4*64*ARS*2)

__global__ __launch_bounds__(256) void k_attn_mma()
{
    const int bh = blockIdx.y, b = bh >> 4, h = bh & 15;
    const int a0 = blockIdx.x * 128;
    extern __shared__ __nv_bfloat16 smb[];
    __nv_bfloat16* sKh = smb;
    __nv_bfloat16* sKl = smb + 64*ARS;
    __nv_bfloat16* sVh = smb + 2*64*ARS;
    __nv_bfloat16* sVl = smb + 3*64*ARS;
    const uint32_t bKh = smem_u32(sKh), bKl = smem_u32(sKl);
    const uint32_t bVh = smem_u32(sVh), bVl = smem_u32(sVl);
    const uint32_t bQ  = bKh;

    const int tid = threadIdx.x, lane = tid & 31, w = tid >> 5;
    const int g = lane >> 2, q = lane & 3, qq2 = q*2;
    const int lr = lane & 7, gb = lane >> 3;
    const uint32_t lof = (uint32_t)((lr + (gb & 1)*8)*(ARS*2) + (gb >> 1)*16);

    const __nv_bfloat16* Qh = g_QUh + ((size_t)bh*CUR + a0)*HD;
    const __nv_bfloat16* Ql = g_QUl + ((size_t)bh*CUR + a0)*HD;
    uint32_t aQh[4][4], aQl[4][4];
    #pragma unroll
    for (int i = 0; i < 4; i++) {
        int s = tid + (i<<8); int row = s >> 3, c = s & 7;
        *(float4*)(smb + row*ARS + c*8) = *(const float4*)(Qh + row*HD + c*8);
    }
    __syncthreads();
    #pragma unroll
    for (int ks = 0; ks < 4; ks++) ldsm4(aQh[ks], bQ + (uint32_t)(w*16*ARS*2) + lof + ks*32);
    __syncthreads();
    #pragma unroll
    for (int i = 0; i < 4; i++) {
        int s = tid + (i<<8); int row = s >> 3, c = s & 7;
        *(float4*)(smb + row*ARS + c*8) = *(const float4*)(Ql + row*HD + c*8);
    }
    __syncthreads();
    #pragma unroll
    for (int ks = 0; ks < 4; ks++) ldsm4(aQl[ks], bQ + (uint32_t)(w*16*ARS*2) + lof + ks*32);

    float oacc[8][4] = {};
    float rm0 = -1e30f, rm1 = -1e30f, rl0 = 0.f, rl1 = 0.f;
    const int arow0 = a0 + w*16 + g;
    const float* P0 = g_P + ((size_t)bh*CUR + arow0)*FULLL;
    const float* P1 = P0 + 8*FULLL;
    const int amax = a0 + w*16 + 15;
    const int nkb = (a0 + 640) >> 6;
    const __nv_bfloat16* Kh = g_Kh + (size_t)bh*FULLL*HD;
    const __nv_bfloat16* Kl = g_Kl + (size_t)bh*FULLL*HD;
    const __nv_bfloat16* Vh = g_Vh + (size_t)bh*FULLL*HD;
    const __nv_bfloat16* Vl = g_Vl + (size_t)bh*FULLL*HD;
    const float CS = 0.125f * 1.44269504f;

    for (int kb = 0; kb < nkb; kb++) {
        const int j0 = kb << 6;
        __syncthreads();
        #pragma unroll
        for (int i = 0; i < 2; i++) {
            int s = tid + (i<<8); int row = s >> 3, c = s & 7;
            int off = row*ARS + c*8;
            size_t gi = (size_t)(j0 + row)*HD + c*8;
            *(float4*)(sKh + off) = *(const float4*)(Kh + gi);
            *(float4*)(sKl + off) = *(const float4*)(Kl + gi);
            *(float4*)(sVh + off) = *(const float4*)(Vh + gi);
            *(float4*)(sVl + off) = *(const float4*)(Vl + gi);
        }
        __syncthreads();
        if (j0 > amax + 512) continue;

        float sacc[8][4] = {};
        #pragma unroll
        for (int n16 = 0; n16 < 4; n16++) {
            #pragma unroll
            for (int ks = 0; ks < 4; ks++) {
                uint32_t kh4[4], kl4[4];
                ldsm4(kh4, bKh + (uint32_t)(n16*16*ARS*2) + lof + ks*32);
                ldsm4(kl4, bKl + (uint32_t)(n16*16*ARS*2) + lof + ks*32);
                mma_bf16(sacc[2*n16],   aQh[ks], kh4[0], kh4[2]);
                mma_bf16(sacc[2*n16+1], aQh[ks], kh4[1], kh4[3]);
                mma_bf16(sacc[2*n16],   aQh[ks], kl4[0], kl4[2]);
                mma_bf16(sacc[2*n16+1], aQh[ks], kl4[1], kl4[3]);
                mma_bf16(sacc[2*n16],   aQl[ks], kh4[0], kh4[2]);
                mma_bf16(sacc[2*n16+1], aQl[ks], kh4[1], kh4[3]);
            }
        }

        #pragma unroll
        for (int nf = 0; nf < 8; nf++) {
            int j = j0 + nf*8 + qq2;
            int m0 = j + (CUR - 1) - arow0;
            int m1 = m0 - 8;
            sacc[nf][0] = (m0     < FULLL) ? (sacc[nf][0] + P0[m0])   * CS : -1e30f;
            sacc[nf][1] = (m0 + 1 < FULLL) ? (sacc[nf][1] + P0[m0+1]) * CS : -1e30f;
            sacc[nf][2] = (m1     < FULLL) ? (sacc[nf][2] + P1[m1])   * CS : -1e30f;
            sacc[nf][3] = (m1 + 1 < FULLL) ? (sacc[nf][3] + P1[m1+1]) * CS : -1e30f;
        }

        float mx0 = -1e30f, mx1 = -1e30f;
        #pragma unroll
        for (int nf = 0; nf < 8; nf++) {
            mx0 = fmaxf(mx0, fmaxf(sacc[nf][0], sacc[nf][1]));
            mx1 = fmaxf(mx1, fmaxf(sacc[nf][2], sacc[nf][3]));
        }
        mx0 = fmaxf(mx0, __shfl_xor_sync(0xffffffffu, mx0, 1));
        mx0 = fmaxf(mx0, __shfl_xor_sync(0xffffffffu, mx0, 2));
        mx1 = fmaxf(mx1, __shfl_xor_sync(0xffffffffu, mx1, 1));
        mx1 = fmaxf(mx1, __shfl_xor_sync(0xffffffffu, mx1, 2));
        float mn0 = fmaxf(rm0, mx0), mn1 = fmaxf(rm1, mx1);
        float cr0 = exp2f(rm0 - mn0), cr1 = exp2f(rm1 - mn1);
        rm0 = mn0; rm1 = mn1;
        float ls0 = 0.f, ls1 = 0.f;
        #pragma unroll
        for (int nf = 0; nf < 8; nf++) {
            float p0 = exp2f(sacc[nf][0] - mn0); sacc[nf][0] = p0; ls0 += p0;
            float p1 = exp2f(sacc[nf][1] - mn0); sacc[nf][1] = p1; ls0 += p1;
            float p2 = exp2f(sacc[nf][2] - mn1); sacc[nf][2] = p2; ls1 += p2;
            float p3 = exp2f(sacc[nf][3] - mn1); sacc[nf][3] = p3; ls1 += p3;
        }
        rl0 = rl0*cr0 + ls0; rl1 = rl1*cr1 + ls1;
        #pragma unroll
        for (int nf = 0; nf < 8; nf++) {
            oacc[nf][0] *= cr0; oacc[nf][1] *= cr0;
            oacc[nf][2] *= cr1; oacc[nf][3] *= cr1;
        }

        #pragma unroll
        for (int kf = 0; kf < 4; kf++) {
            uint32_t aph[4], apl[4];
            split2(sacc[2*kf][0],   sacc[2*kf][1],   aph[0], apl[0]);
            split2(sacc[2*kf][2],   sacc[2*kf][3],   aph[1], apl[1]);
            split2(sacc[2*kf+1][0], sacc[2*kf+1][1], aph[2], apl[2]);
            split2(sacc[2*kf+1][2], sacc[2*kf+1][3], aph[3], apl[3]);
            #pragma unroll
            for (int d16 = 0; d16 < 4; d16++) {
                uint32_t vh4[4], vl4[4];
                ldsm4t(vh4, bVh + (uint32_t)(kf*16*ARS*2) + lof + d16*32);
                ldsm4t(vl4, bVl + (uint32_t)(kf*16*ARS*2) + lof + d16*32);
                mma_bf16(oacc[2*d16],   aph, vh4[0], vh4[1]);
                mma_bf16(oacc[2*d16+1], aph, vh4[2], vh4[3]);
                mma_bf16(oacc[2*d16],   aph, vl4[0], vl4[1]);
                mma_bf16(oacc[2*d16+1], aph, vl4[2], vl4[3]);
                mma_bf16(oacc[2*d16],   apl, vh4[0], vh4[1]);
                mma_bf16(oacc[2*d16+1], apl, vh4[2], vh4[3]);
            }
        }
    }

    rl0 += __shfl_xor_sync(0xffffffffu, rl0, 1);
    rl0 += __shfl_xor_sync(0xffffffffu, rl0, 2);
    rl1 += __shfl_xor_sync(0xffffffffu, rl1, 1);
    rl1 += __shfl_xor_sync(0xffffffffu, rl1, 2);
    float i0 = 1.f / rl0, i1 = 1.f / rl1;
    size_t base0 = ((size_t)arow0*BSZ + b)*(NH*HD) + h*HD;
    size_t base1 = ((size_t)(arow0+8)*BSZ + b)*(NH*HD) + h*HD;
    #pragma unroll
    for (int nf = 0; nf < 8; nf++) {
        int d = nf*8 + qq2;
        uint32_t hi, lo;
        split2(oacc[nf][0]*i0, oacc[nf][1]*i0, hi, lo);
        *(uint32_t*)(g_Ah + base0 + d) = hi;
        *(uint32_t*)(g_Al + base0 + d) = lo;
        split2(oacc[nf][2]*i1, oacc[nf][3]*i1, hi, lo);
        *(uint32_t*)(g_Ah + base1 + d) = hi;
        *(uint32_t*)(g_Al + base1 + d) = lo;
    }
}

// ---------------- launch ----------------
extern "C" void kernel_launch(void* const* d_in, const int* in_sizes, int n_in,
                              void* d_out, int out_size)
{
    const float* inputs     = (const float*)d_in[0];
    const float* pos_emb    = (const float*)d_in[1];
    const float* full_input = (const float*)d_in[2];
    const float* u          = (const float*)d_in[3];
    const float* v          = (const float*)d_in[4];
    // d_in[5] = mask: unused (derived analytically)
    const float* W_kv   = (const float*)d_in[6];
    const float* b_kv   = (const float*)d_in[7];
    const float* W_q    = (const float*)d_in[8];
    const float* b_q    = (const float*)d_in[9];
    const float* W_pos  = (const float*)d_in[10];
    const float* b_pos  = (const float*)d_in[11];
    const float* W_proj = (const float*)d_in[12];
    const float* b_proj = (const float*)d_in[13];
    float* out = (float*)d_out;

    cudaFuncSetAttribute(k_gemm_kv,   cudaFuncAttributeMaxDynamicSharedMemorySize, SM_BYTES);
    cudaFuncSetAttribute(k_gemm_q,    cudaFuncAttributeMaxDynamicSharedMemorySize, SM_BYTES);
    cudaFuncSetAttribute(k_gemm_r,    cudaFuncAttributeMaxDynamicSharedMemorySize, SM_BYTES);
    cudaFuncSetAttribute(k_gemm_pos,  cudaFuncAttributeMaxDynamicSharedMemorySize, SM_BYTES);
    cudaFuncSetAttribute(k_gemm_proj, cudaFuncAttributeMaxDynamicSharedMemorySize, SM_BYTES);

    // KV projection (fused epilogue -> split K/V)
    k_tsplit<<<dim3(64, 32), 256>>>(W_kv, 1024, 2048);
    k_split <<<8192*1024/1024, 256>>>(full_input, 8192*1024);
    k_gemm_kv<<<dim3(16, 64), 256, SM_BYTES>>>(b_kv);

    // Q projection (fused epilogue -> QU/QV split)
    k_tsplit<<<dim3(32, 32), 256>>>(W_q, 1024, 1024);
    k_split <<<4096*1024/1024, 256>>>(inputs, 4096*1024);
    k_gemm_q<<<dim3(8, 32), 256, SM_BYTES>>>(b_q, u, v);

    // R projection (fused epilogue -> Rh/Rl)
    k_tsplit<<<dim3(32, 32), 256>>>(W_pos, 1024, 1024);
    k_split <<<1024*1024/1024, 256>>>(pos_emb, 1024*1024);
    k_gemm_r<<<dim3(8, 8), 256, SM_BYTES>>>(b_pos);

    // P = (q+v) @ r^T per (b,h)
    k_gemm_pos<<<dim3(8, 4, 128), 256, SM_BYTES>>>();

    // attention (writes proj A operand directly)
    k_attn_mma<<<dim3(4, 128), 256, AT_BYTES>>>();

    // output projection (fused bias -> out)
    k_tsplit<<<dim3(32, 32), 256>>>(W_proj, 1024, 1024);
    k_gemm_proj<<<dim3(8, 32), 256, SM_BYTES>>>(b_proj, out);
}